// round 4
// baseline (speedup 1.0000x reference)
#include <cuda_runtime.h>
#include <math.h>

#define WIN_LEN 400
#define WIN_INC 100
#define FFT_LEN 512
#define NFREQ   257             // rfft(512) -> 257 bins
#define KPAD    320             // padded freq count (multiple of 64)
#define NBATCH  16
#define NSAMP   160000
#define NFRAMES 1603            // (160000 + 2*300 - 400)/100 + 1
#define PAD     (WIN_LEN - WIN_INC)   // 300
#define EPSF    1.1920928955078125e-07f

#define FT 32                   // frames per block
#define KT 64                   // freqs per block
#define XS_LEN (WIN_LEN + (FT - 1) * WIN_INC)  // 3500
#define NTHREADS 128
#define WROW (2 * KPAD)         // 640 floats per n-row

// Transposed, padded weights: wT[n][c], c<KPAD real bin c, c>=KPAD imag bin c-KPAD.
__device__ float g_wT[WIN_LEN][WROW];

__global__ void transpose_w_kernel(const float* __restrict__ w) {
    int idx = blockIdx.x * blockDim.x + threadIdx.x;
    if (idx >= WIN_LEN * WROW) return;
    int n = idx / WROW;
    int c = idx % WROW;
    int k_src;
    if (c < KPAD)        k_src = (c < NFREQ) ? c : -1;           // real
    else { int c2 = c - KPAD; k_src = (c2 < NFREQ) ? NFREQ + c2 : -1; }  // imag
    g_wT[n][c] = (k_src >= 0) ? w[(size_t)k_src * WIN_LEN + n] : 0.0f;
}

__global__ __launch_bounds__(NTHREADS) void stft_kernel(
    const float* __restrict__ x, float* __restrict__ out)
{
    __shared__ float xs[XS_LEN];

    const int b  = blockIdx.z;
    const int t0 = blockIdx.x * FT;
    const int k0 = blockIdx.y * KT;
    const int tid = threadIdx.x;

    // Stage signal segment covering 32 overlapping frames.
    const float* xb = x + (size_t)b * NSAMP;
    const int pbase = t0 * WIN_INC - PAD;  // input index of xs[0]
    for (int i = tid; i < XS_LEN; i += NTHREADS) {
        int p = pbase + i;
        xs[i] = (p >= 0 && p < NSAMP) ? __ldg(xb + p) : 0.0f;
    }
    __syncthreads();

    // fqg fastest within warp -> weight loads coalesced across lanes,
    // x loads hit only 2 distinct smem addresses per warp.
    const int fqg = tid & 15;   // 16 freq groups * 4 freqs = 64
    const int fg  = tid >> 4;   // 8 frame groups * 4 frames = 32
    const int kk  = k0 + fqg * 4;

    float ar[4][4], ai[4][4];
#pragma unroll
    for (int f = 0; f < 4; f++)
#pragma unroll
        for (int q = 0; q < 4; q++) { ar[f][q] = 0.0f; ai[f][q] = 0.0f; }

    const float4* __restrict__ wr4 =
        reinterpret_cast<const float4*>(&g_wT[0][kk]);
    const float4* __restrict__ wi4 =
        reinterpret_cast<const float4*>(&g_wT[0][kk + KPAD]);
    const float* xloc = xs + fg * 4 * WIN_INC;

#define ACCUM(f, xv)                                        \
    ar[f][0] = fmaf(xv, r4.x, ar[f][0]);                    \
    ar[f][1] = fmaf(xv, r4.y, ar[f][1]);                    \
    ar[f][2] = fmaf(xv, r4.z, ar[f][2]);                    \
    ar[f][3] = fmaf(xv, r4.w, ar[f][3]);                    \
    ai[f][0] = fmaf(xv, i4.x, ai[f][0]);                    \
    ai[f][1] = fmaf(xv, i4.y, ai[f][1]);                    \
    ai[f][2] = fmaf(xv, i4.z, ai[f][2]);                    \
    ai[f][3] = fmaf(xv, i4.w, ai[f][3]);

#pragma unroll 2
    for (int n = 0; n < WIN_LEN; n++) {
        float4 r4 = __ldg(wr4 + n * (WROW / 4));
        float4 i4 = __ldg(wi4 + n * (WROW / 4));
        float xv0 = xloc[n];
        float xv1 = xloc[n + WIN_INC];
        float xv2 = xloc[n + 2 * WIN_INC];
        float xv3 = xloc[n + 3 * WIN_INC];
        ACCUM(0, xv0)
        ACCUM(1, xv1)
        ACCUM(2, xv2)
        ACCUM(3, xv3)
    }
#undef ACCUM

    // Epilogue: mags then phase (concatenated halves of d_out).
    const size_t phase_off = (size_t)NBATCH * NFREQ * NFRAMES;
#pragma unroll
    for (int f = 0; f < 4; f++) {
        int t = t0 + fg * 4 + f;
        if (t >= NFRAMES) continue;
#pragma unroll
        for (int q = 0; q < 4; q++) {
            int k = kk + q;
            if (k >= NFREQ) continue;
            float r  = ar[f][q];
            float im = ai[f][q];
            float mag = sqrtf(fmaxf(fmaf(r, r, im * im), EPSF));
            float ph  = atan2f(im + EPSF, r + EPSF);
            size_t o = ((size_t)b * NFREQ + k) * NFRAMES + t;
            out[o] = mag;
            out[o + phase_off] = ph;
        }
    }
}

extern "C" void kernel_launch(void* const* d_in, const int* in_sizes, int n_in,
                              void* d_out, int out_size)
{
    const float* x = (const float*)d_in[0];
    const float* w = (const float*)d_in[1];
    // Identify by size: inputs = 16*160000 = 2,560,000; weight = 514*400 = 205,600.
    if (n_in >= 2 && in_sizes[0] == 2 * NFREQ * WIN_LEN) {
        w = (const float*)d_in[0];
        x = (const float*)d_in[1];
    }

    transpose_w_kernel<<<(WIN_LEN * WROW + 255) / 256, 256>>>(w);

    dim3 grid((NFRAMES + FT - 1) / FT, KPAD / KT, NBATCH);
    stft_kernel<<<grid, NTHREADS>>>(x, (float*)d_out);
}

// round 6
// speedup vs baseline: 1.3841x; 1.3841x over previous
#include <cuda_runtime.h>
#include <math.h>

#define WIN_LEN 400
#define WIN_INC 100
#define NFREQ   257             // rfft(512) -> 257 bins
#define KMAIN   256             // bins computed by the main GEMM path
#define NBATCH  16
#define NSAMP   160000
#define NFRAMES 1603
#define PAD     (WIN_LEN - WIN_INC)   // 300
#define EPSF    1.1920928955078125e-07f

#define FT 64                   // frames per block
#define KT 64                   // freqs per block (4 exact tiles of 256)
#define XS_LEN (WIN_LEN + (FT - 1) * WIN_INC)  // 6700 floats = 26.8 KB
#define NTHREADS 128
#define WROW (2 * KMAIN)        // 512 floats per n-row of transposed weight
#define TSTRIDE 65              // smem out-tile row stride (pad for banks)

typedef unsigned long long u64;

// Transposed weights: g_wT[n][c]; c<256 -> real bin c, c>=256 -> imag bin c-256.
__device__ float g_wT[WIN_LEN][WROW];

__global__ void transpose_w_kernel(const float* __restrict__ w) {
    int idx = blockIdx.x * blockDim.x + threadIdx.x;
    if (idx >= WIN_LEN * WROW) return;
    int n = idx / WROW;
    int c = idx % WROW;
    int k_src = (c < KMAIN) ? c : (NFREQ + (c - KMAIN));  // imag bin k -> row 257+k
    g_wT[n][c] = w[(size_t)k_src * WIN_LEN + n];
}

__device__ __forceinline__ u64 pack2(float v) {
    u64 r; asm("mov.b64 %0, {%1, %1};" : "=l"(r) : "f"(v)); return r;
}
__device__ __forceinline__ u64 pack2f(float a, float b) {
    u64 r; asm("mov.b64 %0, {%1, %2};" : "=l"(r) : "f"(a), "f"(b)); return r;
}
__device__ __forceinline__ u64 packu(unsigned a, unsigned b) {
    u64 r; asm("mov.b64 %0, {%1, %2};" : "=l"(r) : "r"(a), "r"(b)); return r;
}
__device__ __forceinline__ void ffma2(u64 &d, u64 a, u64 b) {
    asm("fma.rn.f32x2 %0, %1, %2, %0;" : "+l"(d) : "l"(a), "l"(b));
}
__device__ __forceinline__ float2 unpack2(u64 v) {
    float2 f; asm("mov.b64 {%0, %1}, %2;" : "=f"(f.x), "=f"(f.y) : "l"(v)); return f;
}

__global__ __launch_bounds__(NTHREADS, 4) void stft_kernel(
    const float* __restrict__ x, const float* __restrict__ w,
    float* __restrict__ out)
{
    __shared__ float xs[XS_LEN];   // also reused as the 64x64 output tile

    const int b   = blockIdx.z;
    const int t0  = blockIdx.x * FT;
    const int tid = threadIdx.x;
    const size_t phase_off = (size_t)NBATCH * NFREQ * NFRAMES;

    // ---- Stage signal segment covering 64 overlapping frames ----
    const float* xb = x + (size_t)b * NSAMP;
    const int pbase = t0 * WIN_INC - PAD;
    for (int i = tid; i < XS_LEN; i += NTHREADS) {
        int p = pbase + i;
        xs[i] = (p >= 0 && p < NSAMP) ? __ldg(xb + p) : 0.0f;
    }
    __syncthreads();

    // ---------------- Nyquist path (bin k = 256) ----------------
    if (blockIdx.y == 4) {
        if (tid < FT) {
            const float* wr = w + (size_t)256 * WIN_LEN;   // real row k=256
            const float* wi = w + (size_t)513 * WIN_LEN;   // imag row k=256
            const float* xl = xs + tid * WIN_INC;
            float r = 0.0f, im = 0.0f;
#pragma unroll 4
            for (int n = 0; n < WIN_LEN; n++) {
                float xv = xl[n];
                r  = fmaf(xv, __ldg(wr + n), r);
                im = fmaf(xv, __ldg(wi + n), im);
            }
            int t = t0 + tid;
            if (t < NFRAMES) {
                float mag = sqrtf(fmaxf(fmaf(r, r, im * im), EPSF));
                float ph  = atan2f(im + EPSF, r + EPSF);
                size_t o = ((size_t)b * NFREQ + 256) * NFRAMES + t;
                out[o] = mag;
                out[o + phase_off] = ph;
            }
        }
        return;
    }

    // ---------------- Main path: 64 freqs x 64 frames ----------------
    const int k0  = blockIdx.y * KT;
    const int fqg = tid & 15;          // 16 freq groups * 4 freqs
    const int fg  = tid >> 4;          // 8 frame groups * 8 frames
    const int kk  = k0 + fqg * 4;

    u64 accr[8][2], acci[8][2];
#pragma unroll
    for (int j = 0; j < 8; j++) {
        accr[j][0] = 0ULL; accr[j][1] = 0ULL;
        acci[j][0] = 0ULL; acci[j][1] = 0ULL;
    }

    const uint4* __restrict__ wr4 =
        reinterpret_cast<const uint4*>(&g_wT[0][kk]);
    const uint4* __restrict__ wi4 =
        reinterpret_cast<const uint4*>(&g_wT[0][kk + KMAIN]);
    const float* xloc = xs + fg * 8 * WIN_INC;

#pragma unroll 1
    for (int n0 = 0; n0 < WIN_LEN; n0 += 4) {
        float4 xv[8];
#pragma unroll
        for (int j = 0; j < 8; j++)
            xv[j] = *reinterpret_cast<const float4*>(xloc + j * WIN_INC + n0);
#pragma unroll
        for (int dn = 0; dn < 4; dn++) {
            uint4 rw = __ldg(wr4 + (size_t)(n0 + dn) * (WROW / 4));
            uint4 iw = __ldg(wi4 + (size_t)(n0 + dn) * (WROW / 4));
            u64 r0 = packu(rw.x, rw.y), r1 = packu(rw.z, rw.w);
            u64 i0 = packu(iw.x, iw.y), i1 = packu(iw.z, iw.w);
#pragma unroll
            for (int j = 0; j < 8; j++) {
                float s = (dn == 0) ? xv[j].x : (dn == 1) ? xv[j].y
                        : (dn == 2) ? xv[j].z : xv[j].w;
                u64 sp = pack2(s);
                ffma2(accr[j][0], sp, r0);
                ffma2(accr[j][1], sp, r1);
                ffma2(acci[j][0], sp, i0);
                ffma2(acci[j][1], sp, i1);
            }
        }
    }

    // ---- Epilogue: two passes through the shared tile, coalesced stores ----
    float* tile = xs;   // overlay (main loop done with xs)

    // Pass 1: magnitudes
    __syncthreads();
#pragma unroll
    for (int j = 0; j < 8; j++) {
        int tl = fg * 8 + j;
#pragma unroll
        for (int p = 0; p < 2; p++) {
            float2 r = unpack2(accr[j][p]);
            float2 im = unpack2(acci[j][p]);
            int kl = fqg * 4 + p * 2;
            tile[(kl + 0) * TSTRIDE + tl] =
                sqrtf(fmaxf(fmaf(r.x, r.x, im.x * im.x), EPSF));
            tile[(kl + 1) * TSTRIDE + tl] =
                sqrtf(fmaxf(fmaf(r.y, r.y, im.y * im.y), EPSF));
        }
    }
    __syncthreads();
    for (int i = tid; i < FT * KT; i += NTHREADS) {
        int row = i >> 6, col = i & 63;
        int t = t0 + col;
        if (t < NFRAMES)
            out[((size_t)b * NFREQ + k0 + row) * NFRAMES + t] =
                tile[row * TSTRIDE + col];
    }

    // Pass 2: phases
    __syncthreads();
#pragma unroll
    for (int j = 0; j < 8; j++) {
        int tl = fg * 8 + j;
#pragma unroll
        for (int p = 0; p < 2; p++) {
            float2 r = unpack2(accr[j][p]);
            float2 im = unpack2(acci[j][p]);
            int kl = fqg * 4 + p * 2;
            tile[(kl + 0) * TSTRIDE + tl] = atan2f(im.x + EPSF, r.x + EPSF);
            tile[(kl + 1) * TSTRIDE + tl] = atan2f(im.y + EPSF, r.y + EPSF);
        }
    }
    __syncthreads();
    for (int i = tid; i < FT * KT; i += NTHREADS) {
        int row = i >> 6, col = i & 63;
        int t = t0 + col;
        if (t < NFRAMES)
            out[((size_t)b * NFREQ + k0 + row) * NFRAMES + t + phase_off] =
                tile[row * TSTRIDE + col];
    }
}

extern "C" void kernel_launch(void* const* d_in, const int* in_sizes, int n_in,
                              void* d_out, int out_size)
{
    const float* x = (const float*)d_in[0];
    const float* w = (const float*)d_in[1];
    // Identify by size: signal = 2,560,000 elems; weight = 514*400 = 205,600.
    if (n_in >= 2 && in_sizes[0] == 2 * NFREQ * WIN_LEN) {
        w = (const float*)d_in[0];
        x = (const float*)d_in[1];
    }

    transpose_w_kernel<<<(WIN_LEN * WROW + 255) / 256, 256>>>(w);

    dim3 grid((NFRAMES + FT - 1) / FT, 5, NBATCH);  // y: 4 freq tiles + Nyquist
    stft_kernel<<<grid, NTHREADS>>>(x, w, (float*)d_out);
}